// round 16
// baseline (speedup 1.0000x reference)
#include <cuda_runtime.h>
#include <cuda_fp16.h>
#include <cstdint>

// Problem shapes
#define B_ 16
#define T_ 24
#define N_ 512
#define D_ 128
#define Z_ 12
#define NEG_SLOPE 0.01f

#define MROWS 64           // rows per CTA -> grid 128, 1 CTA/SM
#define NKK 24             // 384 / 16

#define YSTRIDE 132
#define SMEM_BYTES (MROWS * YSTRIDE * 4)   // 33792 (epilogue only)

// fragment-packed operands (filled by prep kernel)
// APK[mtile 512][kk 24][lane 32] : {a0,a1,a2,a3} fp16x2 fragments
// BPK[ntile 16][kk 24][lane 32]  : {bh0,bh1,bl0,bl1}
__device__ uint4 APK[512 * NKK * 32];   // 6.29 MB
__device__ uint4 BPK[16 * NKK * 32];    // 196 KB

__device__ __forceinline__ uint32_t pack_f16(float a, float b) {
    __half2 h = __floats2half2_rn(a, b);
    return *reinterpret_cast<uint32_t*>(&h);
}
__device__ __forceinline__ uint32_t split_hi(float a, float b, uint32_t& lo) {
    __half2 h = __floats2half2_rn(a, b);
    float2 hf = __half22float2(h);
    __half2 l = __floats2half2_rn(a - hf.x, b - hf.y);
    lo = *reinterpret_cast<uint32_t*>(&l);
    return *reinterpret_cast<uint32_t*>(&h);
}
__device__ __forceinline__ void mma16816(float* c, const uint4& a, uint32_t b0, uint32_t b1) {
    asm volatile(
        "mma.sync.aligned.m16n8k16.row.col.f32.f16.f16.f32 "
        "{%0,%1,%2,%3},{%4,%5,%6,%7},{%8,%9},{%0,%1,%2,%3};"
        : "+f"(c[0]), "+f"(c[1]), "+f"(c[2]), "+f"(c[3])
        : "r"(a.x), "r"(a.y), "r"(a.z), "r"(a.w), "r"(b0), "r"(b1));
}

// ---- prep: pack A and W1 into fragment order (identical to R14/R15, verified) ----
__global__ void __launch_bounds__(256)
prep_kernel(const float* __restrict__ Ht, const float* __restrict__ Hs,
            const float* __restrict__ Hm, const float* __restrict__ W1)
{
    int bid = blockIdx.x;
    if (bid < 1536) {      // A: 512 mtiles x 24 kk x 32 lanes
        int idx = bid * 256 + threadIdx.x;          // 0..393215
        int mtile = idx / 768;
        int rem = idx - mtile * 768;
        int kk = rem >> 5, lane = rem & 31;
        int g = lane >> 2, t = lane & 3;
        int row0 = mtile * 16 + g;
        int b = row0 >> 9, n = row0 & 511;
        int kb = kk * 16;
        const float* seg = (kb < 128) ? Ht : ((kb < 256) ? Hs : Hm);
        int ko = (kb & 127) + 2 * t;
        const float* s0 = seg + (((size_t)b * T_ + (T_ - 1)) * N_ + n) * D_ + ko;
        const float* s8 = s0 + 8 * D_;              // row0+8, same b
        uint4 v;
        v.x = pack_f16(s0[0], s0[1]);
        v.y = pack_f16(s8[0], s8[1]);
        v.z = pack_f16(s0[8], s0[9]);
        v.w = pack_f16(s8[8], s8[9]);
        APK[idx] = v;
    } else {               // B: 16 ntiles x 24 kk x 32 lanes
        int idx = (bid - 1536) * 256 + threadIdx.x; // 0..12287
        int nt = idx / 768;
        int rem = idx - nt * 768;
        int kk = rem >> 5, lane = rem & 31;
        int g = lane >> 2, t = lane & 3;
        int col = nt * 8 + g;
        int k0 = kk * 16 + 2 * t;
        const float* w = W1 + (size_t)col * 384 + k0;
        uint32_t bl0, bl1;
        uint32_t bh0 = split_hi(w[0], w[1], bl0);
        uint32_t bh1 = split_hi(w[8], w[9], bl1);
        BPK[idx] = make_uint4(bh0, bh1, bl0, bl1);
    }
}

__global__ void __launch_bounds__(512, 1)
fusion_mma_kernel(const float* __restrict__ b1,   // [128]
                  const float* __restrict__ W2,   // [12][128]
                  const float* __restrict__ b2,   // [12]
                  float* __restrict__ out)        // [16][12][512]
{
    extern __shared__ char smem[];
    const int tid  = threadIdx.x;
    const int wid  = tid >> 5;
    const int lane = tid & 31;
    const int g    = lane >> 2;
    const int t    = lane & 3;
    const int wm   = wid >> 2;       // 0..3 -> mtile, rows wm*16
    const int wn   = wid & 3;        // 0..3 -> cols wn*32
    const int rowBase = blockIdx.x * MROWS;
    const int mtile = blockIdx.x * 4 + wm;

    float acc[4][4];
    #pragma unroll
    for (int j = 0; j < 4; ++j)
        #pragma unroll
        for (int i = 0; i < 4; ++i) acc[j][i] = 0.f;

    const uint4* pA = &APK[mtile * (NKK * 32) + lane];
    const uint4* pB = &BPK[(wn * 4) * (NKK * 32) + lane];

    // ---- mainloop: no smem, no barriers; 3-deep register ring, prefetch dist 2 ----
    uint4 Ar[3], Br[3][4];
    #pragma unroll
    for (int p = 0; p < 2; ++p) {
        Ar[p] = pA[p * 32];
        #pragma unroll
        for (int j = 0; j < 4; ++j) Br[p][j] = pB[j * (NKK * 32) + p * 32];
    }

    #pragma unroll
    for (int kk = 0; kk < NKK; ++kk) {
        const int cur = kk % 3, pf = (kk + 2) % 3;
        if (kk < NKK - 2) {                       // prefetch kk+2 before MMAs of kk
            Ar[pf] = pA[(kk + 2) * 32];
            #pragma unroll
            for (int j = 0; j < 4; ++j) Br[pf][j] = pB[j * (NKK * 32) + (kk + 2) * 32];
        }
        #pragma unroll
        for (int j = 0; j < 4; ++j)               // hi terms (RAW distance 4)
            mma16816(acc[j], Ar[cur], Br[cur][j].x, Br[cur][j].y);
        #pragma unroll
        for (int j = 0; j < 4; ++j)               // lo terms
            mma16816(acc[j], Ar[cur], Br[cur][j].z, Br[cur][j].w);
    }

    // ---- epilogue: bias + LeakyReLU -> Ys smem ----
    float* Ys = reinterpret_cast<float*>(smem);
    {
        int row0 = wm * 16 + g;
        #pragma unroll
        for (int j = 0; j < 4; ++j) {
            int col = wn * 32 + j * 8 + 2 * t;
            float bv0 = __ldg(b1 + col), bv1 = __ldg(b1 + col + 1);
            float y0 = acc[j][0] + bv0; y0 = (y0 > 0.f) ? y0 : NEG_SLOPE * y0;
            float y1 = acc[j][1] + bv1; y1 = (y1 > 0.f) ? y1 : NEG_SLOPE * y1;
            float y2 = acc[j][2] + bv0; y2 = (y2 > 0.f) ? y2 : NEG_SLOPE * y2;
            float y3 = acc[j][3] + bv1; y3 = (y3 > 0.f) ? y3 : NEG_SLOPE * y3;
            *reinterpret_cast<float2*>(Ys + row0 * YSTRIDE + col)       = make_float2(y0, y1);
            *reinterpret_cast<float2*>(Ys + (row0 + 8) * YSTRIDE + col) = make_float2(y2, y3);
        }
    }
    __syncthreads();

    // ---- GEMM2: 64 rows x 12 z = 768 outputs ----
    #pragma unroll
    for (int it = 0; it < 2; ++it) {
        int o = it * 512 + tid;
        if (o < MROWS * Z_) {
            int r = o / Z_, z = o - r * Z_;
            float s = __ldg(b2 + z);
            const float4* w = reinterpret_cast<const float4*>(W2 + (size_t)z * D_);
            const float4* y = reinterpret_cast<const float4*>(Ys + r * YSTRIDE);
            #pragma unroll 8
            for (int d4 = 0; d4 < 32; ++d4) {
                float4 wv = __ldg(w + d4);
                float4 yv = y[d4];
                s += yv.x * wv.x + yv.y * wv.y + yv.z * wv.z + yv.w * wv.w;
            }
            int grp = rowBase + r;
            int b = grp >> 9, n = grp & 511;
            out[((size_t)b * Z_ + z) * N_ + n] = s;
        }
    }
}

extern "C" void kernel_launch(void* const* d_in, const int* in_sizes, int n_in,
                              void* d_out, int out_size)
{
    const float* Ht = (const float*)d_in[0];
    const float* Hs = (const float*)d_in[1];
    const float* Hm = (const float*)d_in[2];
    const float* W1 = (const float*)d_in[3];
    const float* b1 = (const float*)d_in[4];
    const float* W2 = (const float*)d_in[5];
    const float* b2 = (const float*)d_in[6];
    float* out = (float*)d_out;

    prep_kernel<<<1536 + 48, 256>>>(Ht, Hs, Hm, W1);

    cudaFuncSetAttribute(fusion_mma_kernel,
                         cudaFuncAttributeMaxDynamicSharedMemorySize, SMEM_BYTES);
    int grid = (B_ * N_) / MROWS;   // 128 CTAs
    fusion_mma_kernel<<<grid, 512, SMEM_BYTES>>>(b1, W2, b2, out);
}

// round 17
// speedup vs baseline: 1.6038x; 1.6038x over previous
#include <cuda_runtime.h>
#include <cuda_fp16.h>
#include <cstdint>

// Problem shapes
#define B_ 16
#define T_ 24
#define N_ 512
#define D_ 128
#define Z_ 12
#define NEG_SLOPE 0.01f

#define MROWS 64           // rows per CTA -> grid 128, 1 CTA/SM
#define NKK 24             // 384 / 16

#define YSTRIDE 132
#define SMEM_BYTES (MROWS * YSTRIDE * 4)   // 33792 (epilogue only)

// fragment-packed operands (filled by prep kernel)
// APK[mtile 512][kk 24][lane 32] : {a0,a1,a2,a3} fp16x2 fragments
// BPK[ntile 16][kk 24][lane 32]  : {b0,b1} fp16x2 fragments (single fp16)
__device__ uint4 APK[512 * NKK * 32];   // 6.29 MB
__device__ uint2 BPK[16 * NKK * 32];    // 98 KB

__device__ __forceinline__ uint32_t pack_f16(float a, float b) {
    __half2 h = __floats2half2_rn(a, b);
    return *reinterpret_cast<uint32_t*>(&h);
}
__device__ __forceinline__ void mma16816(float* c, const uint4& a, uint32_t b0, uint32_t b1) {
    asm volatile(
        "mma.sync.aligned.m16n8k16.row.col.f32.f16.f16.f32 "
        "{%0,%1,%2,%3},{%4,%5,%6,%7},{%8,%9},{%0,%1,%2,%3};"
        : "+f"(c[0]), "+f"(c[1]), "+f"(c[2]), "+f"(c[3])
        : "r"(a.x), "r"(a.y), "r"(a.z), "r"(a.w), "r"(b0), "r"(b1));
}

// ---- prep: pack A and W1 into fragment order ----
__global__ void __launch_bounds__(256)
prep_kernel(const float* __restrict__ Ht, const float* __restrict__ Hs,
            const float* __restrict__ Hm, const float* __restrict__ W1)
{
    int bid = blockIdx.x;
    if (bid < 1536) {      // A: 512 mtiles x 24 kk x 32 lanes
        int idx = bid * 256 + threadIdx.x;          // 0..393215
        int mtile = idx / 768;
        int rem = idx - mtile * 768;
        int kk = rem >> 5, lane = rem & 31;
        int g = lane >> 2, t = lane & 3;
        int row0 = mtile * 16 + g;
        int b = row0 >> 9, n = row0 & 511;
        int kb = kk * 16;
        const float* seg = (kb < 128) ? Ht : ((kb < 256) ? Hs : Hm);
        int ko = (kb & 127) + 2 * t;
        const float* s0 = seg + (((size_t)b * T_ + (T_ - 1)) * N_ + n) * D_ + ko;
        const float* s8 = s0 + 8 * D_;              // row0+8, same b
        uint4 v;
        v.x = pack_f16(s0[0], s0[1]);
        v.y = pack_f16(s8[0], s8[1]);
        v.z = pack_f16(s0[8], s0[9]);
        v.w = pack_f16(s8[8], s8[9]);
        APK[idx] = v;
    } else {               // B: 16 ntiles x 24 kk x 32 lanes (single fp16)
        int idx = (bid - 1536) * 256 + threadIdx.x; // 0..12287
        int nt = idx / 768;
        int rem = idx - nt * 768;
        int kk = rem >> 5, lane = rem & 31;
        int g = lane >> 2, t = lane & 3;
        int col = nt * 8 + g;
        int k0 = kk * 16 + 2 * t;
        const float* w = W1 + (size_t)col * 384 + k0;
        BPK[idx] = make_uint2(pack_f16(w[0], w[1]), pack_f16(w[8], w[9]));
    }
}

__global__ void __launch_bounds__(512, 1)
fusion_mma_kernel(const float* __restrict__ b1,   // [128]
                  const float* __restrict__ W2,   // [12][128]
                  const float* __restrict__ b2,   // [12]
                  float* __restrict__ out)        // [16][12][512]
{
    extern __shared__ char smem[];
    const int tid  = threadIdx.x;
    const int wid  = tid >> 5;
    const int lane = tid & 31;
    const int g    = lane >> 2;
    const int t    = lane & 3;
    const int wm   = wid >> 2;       // 0..3 -> mtile, rows wm*16
    const int wn   = wid & 3;        // 0..3 -> cols wn*32
    const int rowBase = blockIdx.x * MROWS;
    const int mtile = blockIdx.x * 4 + wm;

    float acc[4][4];
    #pragma unroll
    for (int j = 0; j < 4; ++j)
        #pragma unroll
        for (int i = 0; i < 4; ++i) acc[j][i] = 0.f;

    const uint4* pA = &APK[mtile * (NKK * 32) + lane];
    const uint2* pB = &BPK[(wn * 4) * (NKK * 32) + lane];

    // ---- mainloop: no smem, no barriers; register double-buffer, prefetch dist 1 ----
    uint4 Ar[2];
    uint2 Br[2][4];
    Ar[0] = pA[0];
    #pragma unroll
    for (int j = 0; j < 4; ++j) Br[0][j] = pB[j * (NKK * 32)];

    #pragma unroll
    for (int kk = 0; kk < NKK; ++kk) {
        const int cur = kk & 1, nxt = cur ^ 1;
        if (kk < NKK - 1) {                       // prefetch kk+1 before MMAs of kk
            Ar[nxt] = pA[(kk + 1) * 32];
            #pragma unroll
            for (int j = 0; j < 4; ++j) Br[nxt][j] = pB[j * (NKK * 32) + (kk + 1) * 32];
        }
        #pragma unroll
        for (int j = 0; j < 4; ++j)
            mma16816(acc[j], Ar[cur], Br[cur][j].x, Br[cur][j].y);
    }

    // ---- epilogue: bias + LeakyReLU -> Ys smem ----
    float* Ys = reinterpret_cast<float*>(smem);
    {
        int row0 = wm * 16 + g;
        #pragma unroll
        for (int j = 0; j < 4; ++j) {
            int col = wn * 32 + j * 8 + 2 * t;
            float bv0 = __ldg(b1 + col), bv1 = __ldg(b1 + col + 1);
            float y0 = acc[j][0] + bv0; y0 = (y0 > 0.f) ? y0 : NEG_SLOPE * y0;
            float y1 = acc[j][1] + bv1; y1 = (y1 > 0.f) ? y1 : NEG_SLOPE * y1;
            float y2 = acc[j][2] + bv0; y2 = (y2 > 0.f) ? y2 : NEG_SLOPE * y2;
            float y3 = acc[j][3] + bv1; y3 = (y3 > 0.f) ? y3 : NEG_SLOPE * y3;
            *reinterpret_cast<float2*>(Ys + row0 * YSTRIDE + col)       = make_float2(y0, y1);
            *reinterpret_cast<float2*>(Ys + (row0 + 8) * YSTRIDE + col) = make_float2(y2, y3);
        }
    }
    __syncthreads();

    // ---- GEMM2: 64 rows x 12 z = 768 outputs ----
    #pragma unroll
    for (int it = 0; it < 2; ++it) {
        int o = it * 512 + tid;
        if (o < MROWS * Z_) {
            int r = o / Z_, z = o - r * Z_;
            float s = __ldg(b2 + z);
            const float4* w = reinterpret_cast<const float4*>(W2 + (size_t)z * D_);
            const float4* y = reinterpret_cast<const float4*>(Ys + r * YSTRIDE);
            #pragma unroll 8
            for (int d4 = 0; d4 < 32; ++d4) {
                float4 wv = __ldg(w + d4);
                float4 yv = y[d4];
                s += yv.x * wv.x + yv.y * wv.y + yv.z * wv.z + yv.w * wv.w;
            }
            int grp = rowBase + r;
            int b = grp >> 9, n = grp & 511;
            out[((size_t)b * Z_ + z) * N_ + n] = s;
        }
    }
}

extern "C" void kernel_launch(void* const* d_in, const int* in_sizes, int n_in,
                              void* d_out, int out_size)
{
    const float* Ht = (const float*)d_in[0];
    const float* Hs = (const float*)d_in[1];
    const float* Hm = (const float*)d_in[2];
    const float* W1 = (const float*)d_in[3];
    const float* b1 = (const float*)d_in[4];
    const float* W2 = (const float*)d_in[5];
    const float* b2 = (const float*)d_in[6];
    float* out = (float*)d_out;

    prep_kernel<<<1536 + 48, 256>>>(Ht, Hs, Hm, W1);

    cudaFuncSetAttribute(fusion_mma_kernel,
                         cudaFuncAttributeMaxDynamicSharedMemorySize, SMEM_BYTES);
    int grid = (B_ * N_) / MROWS;   // 128 CTAs
    fusion_mma_kernel<<<grid, 512, SMEM_BYTES>>>(b1, W2, b2, out);
}